// round 4
// baseline (speedup 1.0000x reference)
#include <cuda_runtime.h>
#include <cuda_bf16.h>

// Net_33294586479043: 2-layer GCN ending in log_softmax over axis=1 of a
// [N, 1] tensor. log_softmax over a size-1 axis is exactly 0.0f per element
// (0 - log(exp(0)) = 0, no rounding). The entire GCN is dead code; the
// reference output is 100,000 exact zeros (bit pattern 0x00000000, so a
// byte-wise zero memset is exact).
//
// Rounds 1-3 showed any SM kernel shape lands at a ~3.4-3.9us launch-ramp
// floor (400KB of stores is ~50ns of actual DRAM work; occupancy/issue all
// ~0). This round replaces the kernel with a graph MEMSET node via
// cudaMemsetAsync — async, allocation-free, graph-capturable (captures as a
// memset node, so the graph is non-empty), and it skips the CTA
// rasterization / warp-scheduling ramp entirely.

extern "C" void kernel_launch(void* const* d_in, const int* in_sizes, int n_in,
                              void* d_out, int out_size) {
    (void)d_in; (void)in_sizes; (void)n_in;
    // float32 zeros == all-zero bytes: byte memset is bit-exact.
    cudaMemsetAsync(d_out, 0, (size_t)out_size * sizeof(float), 0);
}

// round 5
// speedup vs baseline: 1.4145x; 1.4145x over previous
#include <cuda_runtime.h>
#include <cuda_bf16.h>

// Net_33294586479043: 2-layer GCN ending in log_softmax over axis=1 of a
// [N, 1] tensor. log_softmax on a size-1 axis is identically 0.0 (exactly,
// even in fp32: x - x - log(exp(0)) = -log(1) = 0). The entire graph
// convolution is dead code; the reference output is 100,000 exact zeros.
//
// Terminal kernel (reverted to the round-1 best, 4.58us total / 3.39us
// kernel). Measured alternatives, all slower or neutral:
//   - 2 stores/thread, 49 blocks:        5.47us  (longer per-warp path)
//   - straight-line 1 store/thread:      5.22us  (noise-level vs R1)
//   - graph memset node (cudaMemsetAsync): 6.88us (driver fill path is
//     costlier per replay than a user SM kernel)
// The kernel is at the single-node graph-replay + launch-ramp floor:
// 400KB of stores is ~50ns of DRAM work; ncu shows DRAM 0.0%, issue 4%.

__global__ void zero_out_kernel(float4* __restrict__ out4, int n4,
                                float* __restrict__ out_tail, int tail_start, int n) {
    int i = blockIdx.x * blockDim.x + threadIdx.x;
    const float4 z = make_float4(0.f, 0.f, 0.f, 0.f);
    // grid-stride over float4 body
    for (int idx = i; idx < n4; idx += gridDim.x * blockDim.x) {
        out4[idx] = z;
    }
    // tail (0..3 elements) handled by thread 0 of block 0
    if (i == 0) {
        for (int t = tail_start; t < n; ++t) out_tail[t] = 0.0f;
    }
}

extern "C" void kernel_launch(void* const* d_in, const int* in_sizes, int n_in,
                              void* d_out, int out_size) {
    (void)d_in; (void)in_sizes; (void)n_in;
    float* out = (float*)d_out;
    int n = out_size;          // 100000 expected
    int n4 = n / 4;            // 25000 float4 stores
    int tail_start = n4 * 4;

    int threads = 256;
    int blocks = (n4 + threads - 1) / threads;
    if (blocks < 1) blocks = 1;

    zero_out_kernel<<<blocks, threads>>>((float4*)out, n4, out, tail_start, n);
}